// round 12
// baseline (speedup 1.0000x reference)
#include <cuda_runtime.h>
#include <cuda_bf16.h>
#include <cstdint>
#include <math.h>

#define S_LEN 4096
#define DM    1024
#define NH    16
#define HD    64
#define WIN   64

// ---------------- device scratch (no allocations allowed) ----------------
__device__ float g_q  [S_LEN * DM];
__device__ float g_k  [S_LEN * DM];
__device__ float g_v  [S_LEN * DM];
__device__ float g_xr [S_LEN * DM];      // tf32-rounded x
__device__ float g_wr [4 * DM * DM];     // tf32-rounded Wq,Wk,Wv,Wo
__device__ float g_aor[S_LEN * DM];      // tf32-rounded attention output

// ---------------- PTX helpers ----------------
__device__ __forceinline__ uint32_t smem_u32(const void* p) {
    uint32_t a;
    asm("{ .reg .u64 t; cvta.to.shared.u64 t, %1; cvt.u32.u64 %0, t; }" : "=r"(a) : "l"(p));
    return a;
}
#define CP16(dst, src) \
    asm volatile("cp.async.cg.shared.global [%0], [%1], 16;" :: "r"((uint32_t)(dst)), "l"(src) : "memory")
#define CP_COMMIT() asm volatile("cp.async.commit_group;" ::: "memory")
#define CP_WAIT1()  asm volatile("cp.async.wait_group 1;" ::: "memory")

#define LDSM4(r, addr) \
    asm volatile("ldmatrix.sync.aligned.m8n8.x4.shared.b16 {%0,%1,%2,%3}, [%4];" \
        : "=r"((r)[0]), "=r"((r)[1]), "=r"((r)[2]), "=r"((r)[3]) : "r"(addr))

#define MMA_TF32(d, a, b0v, b1v) \
    asm volatile("mma.sync.aligned.m16n8k8.row.col.f32.tf32.tf32.f32 " \
        "{%0,%1,%2,%3}, {%4,%5,%6,%7}, {%8,%9}, {%0,%1,%2,%3};" \
        : "+f"((d)[0]), "+f"((d)[1]), "+f"((d)[2]), "+f"((d)[3]) \
        : "r"((a)[0]), "r"((a)[1]), "r"((a)[2]), "r"((a)[3]), "r"(b0v), "r"(b1v))

__device__ __forceinline__ float tf32_rna(float x) {
    uint32_t t;
    asm("cvt.rna.tf32.f32 %0, %1;" : "=r"(t) : "f"(x));
    return __uint_as_float(t);
}

// ---------------- merged tf32 pre-round kernel ----------------
__global__ void round_all(const float* __restrict__ x,
                          const float* __restrict__ Wq, const float* __restrict__ Wk,
                          const float* __restrict__ Wv, const float* __restrict__ Wo,
                          float* __restrict__ xr, float* __restrict__ wr) {
    const int y = blockIdx.y;
    const float* src;
    float* dst;
    if (y < 4) {
        src = x  + (size_t)y * (S_LEN * DM / 4);
        dst = xr + (size_t)y * (S_LEN * DM / 4);
    } else {
        const float* W = y == 4 ? Wq : (y == 5 ? Wk : (y == 6 ? Wv : Wo));
        src = W;
        dst = wr + (size_t)(y - 4) * DM * DM;
    }
    int i = blockIdx.x * blockDim.x + threadIdx.x;
    float4 f = ((const float4*)src)[i];
    ((float4*)dst)[i] = make_float4(tf32_rna(f.x), tf32_rna(f.y), tf32_rna(f.z), tf32_rna(f.w));
}

// ---------------------------------------------------------------------------
// tf32 GEMM v7 (FROZEN from R11): CTA 128x128, BK=32, 3-stage, 2 CTAs/SM,
// in-kernel z-loop (grid=256, no wave tail).
// ---------------------------------------------------------------------------
#define TILE_B  16384
#define STAGE_B (2 * TILE_B)
#define NSTAGE  3
#define GEMM_SMEM (NSTAGE * STAGE_B)  // 98304

__global__ __launch_bounds__(128, 2) void gemm_tf32(
    const float* __restrict__ A, const float* __restrict__ Wr,
    int w_off, int nz,
    float* __restrict__ C0, float* __restrict__ C1, float* __restrict__ C2)
{
    extern __shared__ char sm[];
    const uint32_t smem_base = smem_u32(sm);
    const int tid  = threadIdx.x;
    const int lane = tid & 31;
    const int wid  = tid >> 5;
    const int wm   = wid & 1;
    const int wn   = wid >> 1;
    const int m0 = blockIdx.y * 128;
    const int n0 = blockIdx.x * 128;

    uint32_t swo[8], gA[8], gB[8];
#pragma unroll
    for (int jj = 0; jj < 8; jj++) {
        int qq = tid + 128 * jj;
        int r = qq >> 3, c = qq & 7;
        swo[jj] = (uint32_t)(r * 128 + ((c ^ (r & 7)) << 4));
        gA[jj] = (uint32_t)((m0 + r) * DM + c * 4);
        gB[jj] = (uint32_t)((n0 + r) * DM + c * 4);
    }

    const int lm   = lane >> 3;
    const int lrow = lane & 7;
    const int cSel = lm >> 1;
    uint32_t aOff[4]; int aXor[4];
#pragma unroll
    for (int mi = 0; mi < 4; mi++) {
        int ar = wm * 64 + mi * 16 + (lm & 1) * 8 + lrow;
        aOff[mi] = (uint32_t)(ar * 128); aXor[mi] = ar & 7;
    }
    uint32_t bOff[4]; int bXor[4];
#pragma unroll
    for (int pb = 0; pb < 4; pb++) {
        int br = wn * 64 + pb * 16 + (lm & 1) * 8 + lrow;
        bOff[pb] = (uint32_t)(br * 128); bXor[pb] = br & 7;
    }

    const int ITERS = DM / 32;   // 32

    for (int zi = 0; zi < nz; zi++) {
        const float* B = Wr + (size_t)(w_off + zi) * DM * DM;
        float* C = zi == 0 ? C0 : (zi == 1 ? C1 : C2);

        float acc[4][8][4];
#pragma unroll
        for (int mi = 0; mi < 4; mi++)
#pragma unroll
            for (int nb = 0; nb < 8; nb++)
#pragma unroll
                for (int e2 = 0; e2 < 4; e2++) acc[mi][nb][e2] = 0.0f;

        auto issue = [&](int t) {
            const uint32_t sb = smem_base + (uint32_t)(t % NSTAGE) * STAGE_B;
            const uint32_t kt = (uint32_t)(t * 32);
#pragma unroll
            for (int jj = 0; jj < 8; jj++) {
                CP16(sb + swo[jj],          (const char*)A + (size_t)(gA[jj] + kt) * 4);
                CP16(sb + TILE_B + swo[jj], (const char*)B + (size_t)(gB[jj] + kt) * 4);
            }
            CP_COMMIT();
        };

        __syncthreads();
        issue(0); issue(1);

        for (int t = 0; t < ITERS; t++) {
            CP_WAIT1();
            __syncthreads();
            if (t + 2 < ITERS) issue(t + 2);

            const uint32_t sb = smem_base + (uint32_t)(t % NSTAGE) * STAGE_B;
            const uint32_t aBase = sb, bBase = sb + TILE_B;

#pragma unroll
            for (int s = 0; s < 4; s++) {
                uint32_t fA[4][4];
#pragma unroll
                for (int mi = 0; mi < 4; mi++)
                    LDSM4(fA[mi], aBase + aOff[mi] + (uint32_t)((((2 * s) + cSel) ^ aXor[mi]) << 4));
                uint32_t fB[8][2];
#pragma unroll
                for (int pb = 0; pb < 4; pb++) {
                    uint32_t bt[4];
                    LDSM4(bt, bBase + bOff[pb] + (uint32_t)((((2 * s) + cSel) ^ bXor[pb]) << 4));
                    fB[2 * pb][0] = bt[0]; fB[2 * pb][1] = bt[2];
                    fB[2 * pb + 1][0] = bt[1]; fB[2 * pb + 1][1] = bt[3];
                }
#pragma unroll
                for (int mi = 0; mi < 4; mi++)
#pragma unroll
                    for (int nb = 0; nb < 8; nb++)
                        MMA_TF32(acc[mi][nb], fA[mi], fB[nb][0], fB[nb][1]);
            }
        }

        const int crow0 = m0 + wm * 64 + (lane >> 2);
        const int ccol0 = n0 + wn * 64 + (lane & 3) * 2;
#pragma unroll
        for (int mi = 0; mi < 4; mi++) {
#pragma unroll
            for (int nb = 0; nb < 8; nb++) {
                const int row = crow0 + mi * 16;
                const int col = ccol0 + nb * 8;
                *(float2*)&C[(size_t)row * DM + col]       = make_float2(acc[mi][nb][0], acc[mi][nb][1]);
                *(float2*)&C[(size_t)(row + 8) * DM + col] = make_float2(acc[mi][nb][2], acc[mi][nb][3]);
            }
        }
    }
}

// ---------------------------------------------------------------------------
// Sliding-window attention v5: 4-query sharing.
// Block = 64 queries, 128 threads.  Group of 8 lanes: qg = tid>>3 owns
// queries {4qg..4qg+3}; lane owns d-eighth (chunks l8 and l8+8); e = tid&3
// is the lane's "home" query.  QK: one K-row read per group row serves 4
// queries; 4-shfl reduce-scatter leaves each lane its home query's score.
// AV: p for all 4 queries obtained via 3 shfl_xor (acc indexed by xor-offset
// j -> query e^j, uniform register indexing).  No smem p-exchange phase.
// Conflict-free: 8-lane phases hit chunks (l8 [+8]) of one row = 8 distinct
// 16B banks; group row offset 4*68 floats = 4 mod 8 chunks keeps it distinct.
// ---------------------------------------------------------------------------
#define ATT_PAD 68
#define ATT_ROWS 127
#define ATT_SMEM_BYTES (2 * ATT_ROWS * ATT_PAD * 4)   // 69088

__global__ __launch_bounds__(128, 3) void swattn(
    const float* __restrict__ q, const float* __restrict__ k,
    const float* __restrict__ v, float* __restrict__ o)
{
    extern __shared__ float smf[];
    float* Ks = smf;
    float* Vs = smf + ATT_ROWS * ATT_PAD;

    const int qstart  = blockIdx.x * 64;
    const int h       = blockIdx.y;
    const int korigin = qstart - (WIN - 1);
    const int hcol    = h * HD;

    const int tid = threadIdx.x;
    const int qg  = tid >> 3;      // 0..15: queries 4qg..4qg+3
    const int l8  = tid & 7;       // d-eighth
    const int e   = tid & 3;       // home query within quad
    const int b0  = e & 1;
    const int b1  = (e >> 1) & 1;

    const int c0 = 4 * l8;         // float offset of chunk l8
    const int c1 = 32 + 4 * l8;    // float offset of chunk l8+8

    // ---- load K,V tiles (127 rows x 64 cols), zero-filled below range ----
    for (int i = tid; i < ATT_ROWS * 16; i += 128) {
        const int r  = i >> 4;
        const int c4 = (i & 15) << 2;
        const int g  = korigin + r;
        float4 kk = make_float4(0.f, 0.f, 0.f, 0.f);
        float4 vv = kk;
        if (g >= 0) {
            kk = *(const float4*)&k[(size_t)g * DM + hcol + c4];
            vv = *(const float4*)&v[(size_t)g * DM + hcol + c4];
        }
        *(float4*)&Ks[r * ATT_PAD + c4] = kk;
        *(float4*)&Vs[r * ATT_PAD + c4] = vv;
    }

    // ---- q chunks for all 4 quad queries, pre-scaled by 1/sqrt(hd) ----
    float qreg[4][8];
#pragma unroll
    for (int eq = 0; eq < 4; eq++) {
        const float* qrow = &q[(size_t)(qstart + 4 * qg + eq) * DM + hcol];
        float4 a = *(const float4*)&qrow[c0];
        float4 b = *(const float4*)&qrow[c1];
        qreg[eq][0] = a.x * 0.125f; qreg[eq][1] = a.y * 0.125f;
        qreg[eq][2] = a.z * 0.125f; qreg[eq][3] = a.w * 0.125f;
        qreg[eq][4] = b.x * 0.125f; qreg[eq][5] = b.y * 0.125f;
        qreg[eq][6] = b.z * 0.125f; qreg[eq][7] = b.w * 0.125f;
    }
    __syncthreads();

    // ---- QK: one K row per i serves 4 queries; reduce-scatter over 8 lanes
    float s[67];
#pragma unroll
    for (int i = 0; i < 67; i++) {
        const int r = 4 * qg + i;            // 0..126
        const float* kr = &Ks[r * ATT_PAD];
        float4 ka = *(const float4*)&kr[c0];
        float4 kb = *(const float4*)&kr[c1];
        float P[4];
#pragma unroll
        for (int eq = 0; eq < 4; eq++) {
            float t0 = qreg[eq][0] * ka.x;
            float t1 = qreg[eq][1] * ka.y;
            t0 = fmaf(qreg[eq][2], ka.z, t0);
            t1 = fmaf(qreg[eq][3], ka.w, t1);
            t0 = fmaf(qreg[eq][4], kb.x, t0);
            t1 = fmaf(qreg[eq][5], kb.y, t1);
            t0 = fmaf(qreg[eq][6], kb.z, t0);
            t1 = fmaf(qreg[eq][7], kb.w, t1);
            P[eq] = t0 + t1;
        }
        // reduce-scatter: bit0 split, bit1 split, bit2 combine
        float keep0 = b0 ? P[1] : P[0];      // queries with bit1=0
        float keep1 = b0 ? P[3] : P[2];      // queries with bit1=1
        float send0 = b0 ? P[0] : P[1];
        float send1 = b0 ? P[2] : P[3];
        keep0 += __shfl_xor_sync(0xffffffffu, send0, 1);
        keep1 += __shfl_xor_sync(0xffffffffu, send1, 1);
        float keep = b1 ? keep1 : keep0;
        float send = b1 ? keep0 : keep1;
        keep += __shfl_xor_sync(0xffffffffu, send, 2);
        keep += __shfl_xor_sync(0xffffffffu, keep, 4);
        const bool valid = (i >= e) && (i <= e + 63) && (korigin + r >= 0);
        s[i] = valid ? keep : -INFINITY;
    }

    // ---- softmax over 67 slots (invalid = -inf -> p = 0) ----
    float mx = -INFINITY;
#pragma unroll
    for (int i = 0; i < 67; i++) mx = fmaxf(mx, s[i]);
    float sum = 0.0f;
#pragma unroll
    for (int i = 0; i < 67; i++) { s[i] = __expf(s[i] - mx); sum += s[i]; }
    const float inv = 1.0f / sum;
#pragma unroll
    for (int i = 0; i < 67; i++) s[i] *= inv;

    // ---- AV: one V row per i feeds 4 queries; p via 3 shfl_xor ----
    float acc[4][8];
#pragma unroll
    for (int j = 0; j < 4; j++)
#pragma unroll
        for (int d = 0; d < 8; d++) acc[j][d] = 0.0f;

#pragma unroll
    for (int i = 0; i < 67; i++) {
        const int r = 4 * qg + i;
        const float* vr = &Vs[r * ATT_PAD];
        float4 va = *(const float4*)&vr[c0];
        float4 vb = *(const float4*)&vr[c1];
        float p0 = s[i];                                  // query e
        float p1 = __shfl_xor_sync(0xffffffffu, p0, 1);   // query e^1
        float p2 = __shfl_xor_sync(0xffffffffu, p0, 2);   // query e^2
        float p3 = __shfl_xor_sync(0xffffffffu, p0, 3);   // query e^3
        float pj[4] = {p0, p1, p2, p3};
#pragma unroll
        for (int j = 0; j < 4; j++) {
            const float pw = pj[j];
            acc[j][0] = fmaf(pw, va.x, acc[j][0]);
            acc[j][1] = fmaf(pw, va.y, acc[j][1]);
            acc[j][2] = fmaf(pw, va.z, acc[j][2]);
            acc[j][3] = fmaf(pw, va.w, acc[j][3]);
            acc[j][4] = fmaf(pw, vb.x, acc[j][4]);
            acc[j][5] = fmaf(pw, vb.y, acc[j][5]);
            acc[j][6] = fmaf(pw, vb.z, acc[j][6]);
            acc[j][7] = fmaf(pw, vb.w, acc[j][7]);
        }
    }

    // ---- write tf32-rounded output: acc[j] belongs to query e^j ----
#pragma unroll
    for (int j = 0; j < 4; j++) {
        const int qq = qstart + 4 * qg + (e ^ j);
        float* orow = &o[(size_t)qq * DM + hcol];
        *(float4*)&orow[c0] = make_float4(
            tf32_rna(acc[j][0]), tf32_rna(acc[j][1]),
            tf32_rna(acc[j][2]), tf32_rna(acc[j][3]));
        *(float4*)&orow[c1] = make_float4(
            tf32_rna(acc[j][4]), tf32_rna(acc[j][5]),
            tf32_rna(acc[j][6]), tf32_rna(acc[j][7]));
    }
}

// ---------------- launch ----------------
extern "C" void kernel_launch(void* const* d_in, const int* in_sizes, int n_in,
                              void* d_out, int out_size)
{
    const float* x  = (const float*)d_in[0];
    const float* Wq = (const float*)d_in[1];
    const float* Wk = (const float*)d_in[2];
    const float* Wv = (const float*)d_in[3];
    const float* Wo = (const float*)d_in[4];
    float* out = (float*)d_out;

    float *qp, *kp, *vp, *xr, *wr, *aor;
    cudaGetSymbolAddress((void**)&qp,  g_q);
    cudaGetSymbolAddress((void**)&kp,  g_k);
    cudaGetSymbolAddress((void**)&vp,  g_v);
    cudaGetSymbolAddress((void**)&xr,  g_xr);
    cudaGetSymbolAddress((void**)&wr,  g_wr);
    cudaGetSymbolAddress((void**)&aor, g_aor);

    cudaFuncSetAttribute(gemm_tf32, cudaFuncAttributeMaxDynamicSharedMemorySize, GEMM_SMEM);
    cudaFuncSetAttribute(swattn,    cudaFuncAttributeMaxDynamicSharedMemorySize, ATT_SMEM_BYTES);

    // 1. pre-round x and all W to tf32 (single launch)
    round_all<<<dim3(S_LEN * DM / 4 / 4 / 256, 8), 256>>>(x, Wq, Wk, Wv, Wo, xr, wr);

    // 2. QKV projections: 256 CTAs, 3 weight matrices per CTA (no wave tail)
    gemm_tf32<<<dim3(DM / 128, S_LEN / 128), 128, GEMM_SMEM>>>(xr, wr, 0, 3, qp, kp, vp);

    // 3. sliding-window attention
    swattn<<<dim3(S_LEN / 64, NH), 128, ATT_SMEM_BYTES>>>(qp, kp, vp, aor);

    // 4. output projection
    gemm_tf32<<<dim3(DM / 128, S_LEN / 128), 128, GEMM_SMEM>>>(aor, wr, 3, 1, out, out, out);
}